// round 14
// baseline (speedup 1.0000x reference)
#include <cuda_runtime.h>
#include <cuda_fp16.h>
#include <cstdint>

#define NA 50000
#define NB 50000
#define DD 64
#define FEAT 16
#define EE 30000
#define EPAD 30208     // 236 * 128, padded M for 128-row conv tiles
#define NBLK_C 236     // conv M-tiles per edge type (128 edges each)
#define NCHUNK 65      // 64 weight chunks + 1 bias chunk
#define CHUNK_HALVES 4096   // 64 o-rows x 64 k, 8192 bytes
#define CHUNK_BYTES 8192

// conv dynamic smem layout
#define SM_H     0            // 128*72 halves = 18432 B
#define SM_BUF   18432        // 3 * 8192 B = 24576
#define SM_MBAR  43008        // 3 full + 3 empty mbarriers = 48 B
#define CONV_SMEM 43056

#define SXW 68   // padded fp32 row stride (64-wide tiles): 16B-aligned, conflict-free
#define SEW 20   // padded fp32 row stride (16-wide tiles)

// ---------------- scratch (static device globals; no allocs) ----------------
__device__ float  g_xa0[NA * DD];
__device__ float  g_xb0[NB * DD];
__device__ float  g_xa1[NA * DD];
__device__ float  g_xb1[NB * DD];
__device__ __half g_hab[EPAD * DD];      // edge-MLP hidden, fp16, zero-padded rows
__device__ __half g_hba[EPAD * DD];
__device__ __half g_wn_ab[NCHUNK * CHUNK_HALVES];  // chunk-major packed W2v, SW128-swizzled
__device__ __half g_wn_ba[NCHUNK * CHUNK_HALVES];
__device__ float  g_ss[(NA + NB) * DD];  // ssa = g_ss, ssb = g_ss + NA*DD
__device__ float  g_cnt[NA + NB];        // cnta = g_cnt, cntb = g_cnt + NA

// ---------------- helpers ----------------
__device__ __forceinline__ uint32_t smem_u32(const void* p) {
    uint32_t a;
    asm("{ .reg .u64 t; cvta.to.shared.u64 t, %1; cvt.u32.u64 %0, t; }" : "=r"(a) : "l"(p));
    return a;
}

__device__ __forceinline__ void ldsm_x4(uint32_t& r0, uint32_t& r1, uint32_t& r2, uint32_t& r3,
                                        uint32_t addr) {
    asm volatile("ldmatrix.sync.aligned.m8n8.x4.shared.b16 {%0,%1,%2,%3}, [%4];"
                 : "=r"(r0), "=r"(r1), "=r"(r2), "=r"(r3) : "r"(addr));
}

__device__ __forceinline__ void mma16816(float* d, const uint32_t* a, const uint32_t* b) {
    asm volatile(
        "mma.sync.aligned.m16n8k16.row.col.f32.f16.f16.f32 "
        "{%0,%1,%2,%3}, {%4,%5,%6,%7}, {%8,%9}, {%0,%1,%2,%3};"
        : "+f"(d[0]), "+f"(d[1]), "+f"(d[2]), "+f"(d[3])
        : "r"(a[0]), "r"(a[1]), "r"(a[2]), "r"(a[3]), "r"(b[0]), "r"(b[1]));
}

__device__ __forceinline__ uint32_t f2h2(float x, float y) {
    __half2 h = __floats2half2_rn(x, y);
    return *(uint32_t*)&h;
}

__device__ __forceinline__ uint32_t hmul2u(uint32_t a, uint32_t s) {
    __half2 r = __hmul2(*(__half2*)&a, *(__half2*)&s);
    return *(uint32_t*)&r;
}

__device__ __forceinline__ void mbar_wait(uint32_t mbar, uint32_t parity) {
    uint32_t done;
    asm volatile(
        "{\n\t.reg .pred p;\n\t"
        "mbarrier.try_wait.parity.shared.b64 p, [%1], %2;\n\t"
        "selp.b32 %0, 1, 0, p;\n\t}"
        : "=r"(done) : "r"(mbar), "r"(parity) : "memory");
    if (!done) {
        asm volatile(
            "{\n\t.reg .pred P1;\n\t"
            "WL_%=:\n\t"
            "mbarrier.try_wait.parity.shared.b64 P1, [%0], %1, 0x989680;\n\t"
            "@P1 bra.uni WD_%=;\n\t"
            "bra.uni WL_%=;\n\t"
            "WD_%=:\n\t}"
            :: "r"(mbar), "r"(parity) : "memory");
    }
}

// ---------------- utility kernels ----------------
__global__ void k_zero(float* __restrict__ p, int n) {
    int i = blockIdx.x * 256 + threadIdx.x;
    if (i < n) p[i] = 0.f;
}

// zero ss + cnt in one launch
__global__ void k_zero2(float* __restrict__ ss, float* __restrict__ cnt) {
    int i = blockIdx.x * 256 + threadIdx.x;
    const int SSN = (NA + NB) * DD;
    if (i < SSN) ss[i] = 0.f;
    else if (i < SSN + NA + NB) cnt[i - SSN] = 0.f;
}

__global__ void k_count2(const int* __restrict__ dst_ab, const int* __restrict__ dst_ba,
                         float* __restrict__ cnta, float* __restrict__ cntb) {
    int i = blockIdx.x * 256 + threadIdx.x;
    if (i < EE) atomicAdd(&cntb[dst_ab[i]], 1.f);
    else if (i < 2 * EE) atomicAdd(&cnta[dst_ba[i - EE]], 1.f);
}

// pack W2 + b2 into chunk-major, SW128-swizzled layout — tiled transpose.
__global__ void __launch_bounds__(256) k_pack2(
    const float* __restrict__ W2a, const float* __restrict__ b2a, __half* __restrict__ WNa,
    const float* __restrict__ W2b, const float* __restrict__ b2b, __half* __restrict__ WNb)
{
    __shared__ float sT[64 * SXW];   // [ki][o], padded
    int bid = blockIdx.x;
    const float* W2; const float* b2; __half* WN;
    if (bid < NCHUNK) { W2 = W2a; b2 = b2a; WN = WNa; }
    else { bid -= NCHUNK; W2 = W2b; b2 = b2b; WN = WNb; }
    const int chunk = bid;
    const float* src = (chunk < 64) ? (W2 + (size_t)chunk * 4096) : b2;
    const int tid = threadIdx.x;

#pragma unroll
    for (int j = 0; j < 4; j++) {
        int li = tid + 256 * j;
        int ki = li >> 4, o4 = (li & 15) * 4;
        float4 v = *(const float4*)(src + ki * 64 + o4);
        *(float4*)(sT + ki * SXW + o4) = v;
    }
    __syncthreads();

    __half* dst = WN + (size_t)chunk * CHUNK_HALVES;
#pragma unroll
    for (int j = 0; j < 8; j++) {
        int w = tid * 8 + j;
        int o = w >> 5, kp = w & 31;
        __half2 h = __floats2half2_rn(sT[(2 * kp) * SXW + o], sT[(2 * kp + 1) * SXW + o]);
        uint32_t boff = (uint32_t)(o * 128 + kp * 4);
        boff ^= (boff >> 3) & 0x70;
        *(__half2*)((char*)dst + boff) = h;
    }
}

// ---------------- merged node-linear + edge-MLP ----------------
__global__ void __launch_bounds__(256) k_ne(
    const float* __restrict__ emb_a, const int* __restrict__ x_a,
    const float* __restrict__ Wn_a, const float* __restrict__ bn_a, float* __restrict__ xa0,
    const float* __restrict__ emb_b, const int* __restrict__ x_b,
    const float* __restrict__ Wn_b, const float* __restrict__ bn_b, float* __restrict__ xb0,
    const float* __restrict__ ea_ab, const float* __restrict__ W1_ab,
    const float* __restrict__ b1_ab, __half* __restrict__ hab,
    const float* __restrict__ ea_ba, const float* __restrict__ W1_ba,
    const float* __restrict__ b1_ba, __half* __restrict__ hba)
{
    __shared__ __align__(16) float pool[8512];
    float* sW = pool;
    float* sB = pool + 4096;
    float* sX = pool + 4160;
    int bid = blockIdx.x;
    int tid = threadIdx.x;

    if (bid < 1564) {
        const float* X; const int* idx; const float* W; const float* b; float* Y; int N;
        if (bid < 782) { X = emb_a; idx = x_a; W = Wn_a; b = bn_a; Y = xa0; N = NA; }
        else { bid -= 782; X = emb_b; idx = x_b; W = Wn_b; b = bn_b; Y = xb0; N = NB; }
        for (int i = tid; i < 1024; i += 256)
            ((float4*)sW)[i] = ((const float4*)W)[i];
        if (tid < 64) sB[tid] = b[tid];
        int n0 = bid * 64;
        int r = tid >> 2, c0 = (tid & 3) * 16;
        int n = n0 + r;
        {
            float4* sxp = (float4*)(sX + r * SXW + c0);
            if (n < N) {
                int s = idx[n];
                const float4* xr = (const float4*)(X + (size_t)s * 64 + c0);
#pragma unroll
                for (int k = 0; k < 4; k++) sxp[k] = xr[k];
            } else {
                float4 z = {0.f, 0.f, 0.f, 0.f};
#pragma unroll
                for (int k = 0; k < 4; k++) sxp[k] = z;
            }
        }
        __syncthreads();
        int o0 = (tid & 3) * 16;
        float acc[16];
#pragma unroll
        for (int j = 0; j < 16; j++) acc[j] = sB[o0 + j];
        const float* sxr = sX + r * SXW;
#pragma unroll 8
        for (int d = 0; d < 64; d++) {
            float xv = sxr[d];
            const float4* wr = (const float4*)(sW + d * 64 + o0);
            float4 w0 = wr[0], w1 = wr[1], w2 = wr[2], w3 = wr[3];
            acc[0]  += xv * w0.x; acc[1]  += xv * w0.y; acc[2]  += xv * w0.z; acc[3]  += xv * w0.w;
            acc[4]  += xv * w1.x; acc[5]  += xv * w1.y; acc[6]  += xv * w1.z; acc[7]  += xv * w1.w;
            acc[8]  += xv * w2.x; acc[9]  += xv * w2.y; acc[10] += xv * w2.z; acc[11] += xv * w2.w;
            acc[12] += xv * w3.x; acc[13] += xv * w3.y; acc[14] += xv * w3.z; acc[15] += xv * w3.w;
        }
        if (n < N) {
            float4* yp = (float4*)(Y + (size_t)n * 64 + o0);
#pragma unroll
            for (int k = 0; k < 4; k++) {
                float4 v = {acc[4 * k], acc[4 * k + 1], acc[4 * k + 2], acc[4 * k + 3]};
                yp[k] = v;
            }
        }
    } else {
        bid -= 1564;
        const float* EA; const float* W1; const float* b1; __half* H;
        if (bid < 472) { EA = ea_ab; W1 = W1_ab; b1 = b1_ab; H = hab; }
        else { bid -= 472; EA = ea_ba; W1 = W1_ba; b1 = b1_ba; H = hba; }
        if (tid < 256) ((float4*)sW)[tid] = ((const float4*)W1)[tid];
        if (tid < 64) sB[tid] = b1[tid];
        int e0 = bid * 64;
        int r = tid >> 2, c0 = (tid & 3) * 4;
        int e = e0 + r;
        {
            float4* sxp = (float4*)(sX + r * SEW + c0);
            if (e < EE) {
                sxp[0] = *(const float4*)(EA + (size_t)e * 16 + c0);
            } else {
                float4 z = {0.f, 0.f, 0.f, 0.f};
                sxp[0] = z;
            }
        }
        __syncthreads();
        int o0 = (tid & 3) * 16;
        float acc[16];
#pragma unroll
        for (int j = 0; j < 16; j++) acc[j] = sB[o0 + j];
        const float* sxr = sX + r * SEW;
#pragma unroll
        for (int d = 0; d < 16; d++) {
            float xv = sxr[d];
            const float4* wr = (const float4*)(sW + d * 64 + o0);
            float4 w0 = wr[0], w1 = wr[1], w2 = wr[2], w3 = wr[3];
            acc[0]  += xv * w0.x; acc[1]  += xv * w0.y; acc[2]  += xv * w0.z; acc[3]  += xv * w0.w;
            acc[4]  += xv * w1.x; acc[5]  += xv * w1.y; acc[6]  += xv * w1.z; acc[7]  += xv * w1.w;
            acc[8]  += xv * w2.x; acc[9]  += xv * w2.y; acc[10] += xv * w2.z; acc[11] += xv * w2.w;
            acc[12] += xv * w3.x; acc[13] += xv * w3.y; acc[14] += xv * w3.z; acc[15] += xv * w3.w;
        }
        {
            __half2 h[8];
            if (e < EE) {
#pragma unroll
                for (int j = 0; j < 8; j++)
                    h[j] = __floats2half2_rn(fmaxf(acc[2 * j], 0.f), fmaxf(acc[2 * j + 1], 0.f));
            } else {
#pragma unroll
                for (int j = 0; j < 8; j++) h[j] = __floats2half2_rn(0.f, 0.f);
            }
            uint4* hp = (uint4*)(H + (size_t)e * 64 + o0);
            const uint4* hs = (const uint4*)h;
            hp[0] = hs[0]; hp[1] = hs[1];
        }
    }
}

// ---------------- fused conv: 128 edges/CTA, 8 warps x 16 rows, 3 CTAs/SM.
// B chunks via cp.async.bulk + mbarrier, triple-buffered, decoupled warps.
__global__ void __launch_bounds__(256, 3) k_conv2(
    const float* __restrict__ Xa, const __half* __restrict__ Ha,
    const __half* __restrict__ WNa, const int* __restrict__ SRCa,
    const int* __restrict__ DSTa, float* __restrict__ SSa,
    const float* __restrict__ Xb, const __half* __restrict__ Hb,
    const __half* __restrict__ WNb, const int* __restrict__ SRCb,
    const int* __restrict__ DSTb, float* __restrict__ SSb)
{
    extern __shared__ __align__(16) char dsm[];
    __half* sH = (__half*)(dsm + SM_H);             // 128 x 72 halves
    int bid = blockIdx.x;
    const float* X; const __half* H; const __half* WN;
    const int* SRC; const int* DST; float* SS;
    if (bid < NBLK_C) { X = Xa; H = Ha; WN = WNa; SRC = SRCa; DST = DSTa; SS = SSa; }
    else { bid -= NBLK_C; X = Xb; H = Hb; WN = WNb; SRC = SRCb; DST = DSTb; SS = SSb; }

    const int tid = threadIdx.x, lane = tid & 31, wid = tid >> 5;
    const int e0 = bid * 128;
    const uint32_t sBuf = smem_u32(dsm + SM_BUF);
    const uint32_t mfull = smem_u32(dsm + SM_MBAR);
    const uint32_t mempty = mfull + 24;

    if (tid == 0) {
#pragma unroll
        for (int b = 0; b < 3; b++) {
            asm volatile("mbarrier.init.shared.b64 [%0], %1;" :: "r"(mfull + b * 8), "r"(1u) : "memory");
            asm volatile("mbarrier.init.shared.b64 [%0], %1;" :: "r"(mempty + b * 8), "r"(8u) : "memory");
        }
    }

    // stage H tile: 128 rows x 64 halves -> padded stride 72 (1024 x 16B)
    {
        const uint4* hg = (const uint4*)(H + (size_t)e0 * 64);
#pragma unroll
        for (int i = 0; i < 4; i++) {
            int idx = tid + 256 * i;
            int row = idx >> 3, seg = idx & 7;
            *(uint4*)((char*)sH + (row * 72 + seg * 8) * 2) = hg[idx];
        }
    }
    __syncthreads();   // mbar init + sH visible

#define BULK_ISSUE(c) do {                                                        \
        uint32_t mb_ = mfull + ((c) % 3) * 8;                                     \
        asm volatile("mbarrier.arrive.expect_tx.shared.b64 _, [%0], %1;"          \
                     :: "r"(mb_), "r"((uint32_t)CHUNK_BYTES) : "memory");         \
        asm volatile("cp.async.bulk.shared::cta.global.mbarrier::complete_tx::bytes " \
                     "[%0], [%1], %2, [%3];"                                      \
                     :: "r"(sBuf + ((c) % 3) * CHUNK_BYTES),                      \
                        "l"(WN + (size_t)(c) * CHUNK_HALVES),                     \
                        "r"((uint32_t)CHUNK_BYTES), "r"(mb_) : "memory");         \
    } while (0)

    if (tid == 0) { BULK_ISSUE(0); BULK_ISSUE(1); }

    // 2 row slots per thread: rbase, rbase+8
    const int rbase = wid * 16 + (lane >> 2);
    const int m2 = (lane & 3) * 2;
    const int eg0 = e0 + rbase, eg1 = e0 + rbase + 8;
    const int s0 = (eg0 < EE) ? SRC[eg0] : 0;
    const int s1 = (eg1 < EE) ? SRC[eg1] : 0;

    // x fragments (fp16, register-resident for whole K loop)
    uint32_t xF[4][4];
    {
        const float* xp0 = X + (size_t)s0 * 64;
        const float* xp1 = X + (size_t)s1 * 64;
#pragma unroll
        for (int ks = 0; ks < 4; ks++) {
            float2 v;
            v = *(const float2*)(xp0 + ks * 16 + m2);     xF[ks][0] = f2h2(v.x, v.y);
            v = *(const float2*)(xp1 + ks * 16 + m2);     xF[ks][1] = f2h2(v.x, v.y);
            v = *(const float2*)(xp0 + ks * 16 + m2 + 8); xF[ks][2] = f2h2(v.x, v.y);
            v = *(const float2*)(xp1 + ks * 16 + m2 + 8); xF[ks][3] = f2h2(v.x, v.y);
        }
    }

    float acc[8][4];
#pragma unroll
    for (int j = 0; j < 8; j++)
#pragma unroll
        for (int q = 0; q < 4; q++) acc[j][q] = 0.f;

    for (int kc = 0; kc < NCHUNK; kc++) {
        if (tid == 0) {
            if (kc == 0) {
                BULK_ISSUE(2);
            } else if (kc + 2 < NCHUNK) {
                mbar_wait(mempty + ((kc - 1) % 3) * 8, (uint32_t)(((kc - 1) / 3) & 1));
                BULK_ISSUE(kc + 2);
            }
        }
        mbar_wait(mfull + (kc % 3) * 8, (uint32_t)((kc / 3) & 1));

        uint32_t sc0, sc1;
        if (kc < 64) {
            __half2 t0 = __half2half2(sH[rbase * 72 + kc]);
            __half2 t1 = __half2half2(sH[(rbase + 8) * 72 + kc]);
            sc0 = *(uint32_t*)&t0; sc1 = *(uint32_t*)&t1;
        } else {
            __half2 one = __floats2half2_rn(1.f, 1.f);
            sc0 = sc1 = *(uint32_t*)&one;
        }

        const uint32_t bufb = sBuf + (kc % 3) * CHUNK_BYTES;
#pragma unroll
        for (int ks = 0; ks < 4; ks++) {
            uint32_t aR[4];
            aR[0] = hmul2u(xF[ks][0], sc0);
            aR[1] = hmul2u(xF[ks][1], sc1);
            aR[2] = hmul2u(xF[ks][2], sc0);
            aR[3] = hmul2u(xF[ks][3], sc1);
#pragma unroll
            for (int p = 0; p < 4; p++) {
                int r = p * 16 + (lane & 15);
                uint32_t off = (uint32_t)(r * 128 + (ks * 16 + ((lane >> 4) << 3)) * 2);
                off ^= (off >> 3) & 0x70;
                uint32_t b0[2], b1[2];
                ldsm_x4(b0[0], b1[0], b0[1], b1[1], bufb + off);
                mma16816(acc[2 * p],     aR, b0);
                mma16816(acc[2 * p + 1], aR, b1);
            }
        }
        if (lane == 0)
            asm volatile("mbarrier.arrive.shared.b64 _, [%0];"
                         :: "r"(mempty + (kc % 3) * 8) : "memory");
    }
#undef BULK_ISSUE

    const int d0 = (eg0 < EE) ? DST[eg0] : -1;
    const int d1 = (eg1 < EE) ? DST[eg1] : -1;
#pragma unroll
    for (int j = 0; j < 8; j++) {
        int c = j * 8 + m2;
        if (d0 >= 0) {
            atomicAdd(&SS[(size_t)d0 * 64 + c],     acc[j][0]);
            atomicAdd(&SS[(size_t)d0 * 64 + c + 1], acc[j][1]);
        }
        if (d1 >= 0) {
            atomicAdd(&SS[(size_t)d1 * 64 + c],     acc[j][2]);
            atomicAdd(&SS[(size_t)d1 * 64 + c + 1], acc[j][3]);
        }
    }
}

// Y[n,:] = relu( SS[n,:]/max(cnt,1) + Xprev[n,:] @ root + bias )  (UNCHANGED)
__global__ void __launch_bounds__(256) k_finalize2(
    const float* __restrict__ Xb_, const float* __restrict__ SSb_,
    const float* __restrict__ CNTb_, const float* __restrict__ Wab,
    const float* __restrict__ bab, float* __restrict__ Yb_,
    const float* __restrict__ Xa_, const float* __restrict__ SSa_,
    const float* __restrict__ CNTa_, const float* __restrict__ Wba,
    const float* __restrict__ bba, float* __restrict__ Ya_)
{
    __shared__ float sW[64 * 64];
    __shared__ float sB[64];
    __shared__ float sX[64 * SXW];
    int bid = blockIdx.x;
    const float* Xp; const float* SS; const float* CNT; const float* W; const float* b;
    float* Y; int N;
    if (bid < 782) { Xp = Xb_; SS = SSb_; CNT = CNTb_; W = Wab; b = bab; Y = Yb_; N = NB; }
    else { bid -= 782; Xp = Xa_; SS = SSa_; CNT = CNTa_; W = Wba; b = bba; Y = Ya_; N = NA; }
    int tid = threadIdx.x;
    for (int i = tid; i < 1024; i += 256)
        ((float4*)sW)[i] = ((const float4*)W)[i];
    if (tid < 64) sB[tid] = b[tid];
    int n0 = bid * 64;
    int r = tid >> 2, c0 = (tid & 3) * 16;
    int n = n0 + r;
    {
        float4* sxp = (float4*)(sX + r * SXW + c0);
        if (n < N) {
            const float4* xr = (const float4*)(Xp + (size_t)n * 64 + c0);
#pragma unroll
            for (int k = 0; k < 4; k++) sxp[k] = xr[k];
        } else {
            float4 z = {0.f, 0.f, 0.f, 0.f};
#pragma unroll
            for (int k = 0; k < 4; k++) sxp[k] = z;
        }
    }
    __syncthreads();
    int o0 = (tid & 3) * 16;
    float acc[16];
#pragma unroll
    for (int j = 0; j < 16; j++) acc[j] = sB[o0 + j];
    const float* sxr = sX + r * SXW;
#pragma unroll 8
    for (int d = 0; d < 64; d++) {
        float xv = sxr[d];
        const float4* wr = (const float4*)(sW + d * 64 + o0);
        float4 w0 = wr[0], w1 = wr[1], w2 = wr[2], w3 = wr[3];
        acc[0]  += xv * w0.x; acc[1]  += xv * w0.y; acc[2]  += xv * w0.z; acc[3]  += xv * w0.w;
        acc[4]  += xv * w1.x; acc[5]  += xv * w1.y; acc[6]  += xv * w1.z; acc[7]  += xv * w1.w;
        acc[8]  += xv * w2.x; acc[9]  += xv * w2.y; acc[10] += xv * w2.z; acc[11] += xv * w2.w;
        acc[12] += xv * w3.x; acc[13] += xv * w3.y; acc[14] += xv * w3.z; acc[15] += xv * w3.w;
    }
    if (n < N) {
        float ic = 1.f / fmaxf(CNT[n], 1.f);
        const float4* sp = (const float4*)(SS + (size_t)n * 64 + o0);
        float4* yp = (float4*)(Y + (size_t)n * 64 + o0);
#pragma unroll
        for (int k = 0; k < 4; k++) {
            float4 s = sp[k];
            float4 v;
            v.x = fmaxf(acc[4 * k + 0] + s.x * ic, 0.f);
            v.y = fmaxf(acc[4 * k + 1] + s.y * ic, 0.f);
            v.z = fmaxf(acc[4 * k + 2] + s.z * ic, 0.f);
            v.w = fmaxf(acc[4 * k + 3] + s.w * ic, 0.f);
            yp[k] = v;
        }
    }
}

// ---------------- launcher ----------------
static void* sym(const void* s) {
    void* p = nullptr;
    cudaGetSymbolAddress(&p, s);
    return p;
}

extern "C" void kernel_launch(void* const* d_in, const int* in_sizes, int n_in,
                              void* d_out, int out_size)
{
    const int*   x_a      = (const int*)d_in[0];
    const int*   x_b      = (const int*)d_in[1];
    const int*   ei_ab    = (const int*)d_in[2];   // [2,E]
    const int*   ei_ba    = (const int*)d_in[3];
    const float* ea_ab    = (const float*)d_in[4];
    const float* ea_ba    = (const float*)d_in[5];
    const float* emb_a    = (const float*)d_in[6];
    const float* emb_b    = (const float*)d_in[7];
    const float* Wn_a     = (const float*)d_in[8];
    const float* bn_a     = (const float*)d_in[9];
    const float* Wn_b     = (const float*)d_in[10];
    const float* bn_b     = (const float*)d_in[11];
    const float* W1_ab    = (const float*)d_in[12];
    const float* b1_ab    = (const float*)d_in[13];
    const float* W2_ab    = (const float*)d_in[14];
    const float* b2_ab    = (const float*)d_in[15];
    const float* W1_ba    = (const float*)d_in[16];
    const float* b1_ba    = (const float*)d_in[17];
    const float* W2_ba    = (const float*)d_in[18];
    const float* b2_ba    = (const float*)d_in[19];
    const float* root0_ab = (const float*)d_in[20];
    const float* bias0_ab = (const float*)d_in[21];
    const float* root0_ba = (const float*)d_in[22];
    const float* bias0_ba = (const float*)d_in[23];
    const float* root1_ab = (const float*)d_in[24];
    const float* bias1_ab = (const float*)d_in[25];
    const float* root1_ba = (const float*)d_in[26];
    const float* bias1_ba = (const float*)d_in[27];

    float*  xa0 = (float*)sym(g_xa0);
    float*  xb0 = (float*)sym(g_xb0);
    float*  xa1 = (float*)sym(g_xa1);
    float*  xb1 = (float*)sym(g_xb1);
    __half* hab = (__half*)sym(g_hab);
    __half* hba = (__half*)sym(g_hba);
    __half* wnab = (__half*)sym(g_wn_ab);
    __half* wnba = (__half*)sym(g_wn_ba);
    float*  ss  = (float*)sym(g_ss);
    float*  cnt = (float*)sym(g_cnt);
    float*  ssa = ss;
    float*  ssb = ss + (size_t)NA * DD;
    float*  cnta = cnt;
    float*  cntb = cnt + NA;

    const int* src_ab = ei_ab;
    const int* dst_ab = ei_ab + EE;
    const int* src_ba = ei_ba;
    const int* dst_ba = ei_ba + EE;

    float* out = (float*)d_out;

    cudaFuncSetAttribute(k_conv2, cudaFuncAttributeMaxDynamicSharedMemorySize, CONV_SMEM);

    // 1. zero ss + cnt
    const int ZN = (NA + NB) * DD + (NA + NB);
    k_zero2<<<(ZN + 255) / 256, 256>>>(ss, cnt);

    // 2. pack W2+b2 (tiled transpose, coalesced)
    k_pack2<<<2 * NCHUNK, 256>>>(W2_ab, b2_ab, wnab, W2_ba, b2_ba, wnba);

    // 3. node features + edge MLP (merged)
    k_ne<<<2508, 256>>>(emb_a, x_a, Wn_a, bn_a, xa0,
                        emb_b, x_b, Wn_b, bn_b, xb0,
                        ea_ab, W1_ab, b1_ab, hab,
                        ea_ba, W1_ba, b1_ba, hba);

    // 4. conv layer 0  (<- ncu profiles this launch)
    k_conv2<<<2 * NBLK_C, 256, CONV_SMEM>>>(xa0, hab, wnab, src_ab, dst_ab, ssb,
                                            xb0, hba, wnba, src_ba, dst_ba, ssa);

    // 5. counts (consumed only by finalize)
    k_count2<<<(2 * EE + 255) / 256, 256>>>(dst_ab, dst_ba, cnta, cntb);

    // 6. finalize layer 0
    k_finalize2<<<1564, 256>>>(xb0, ssb, cntb, root0_ab, bias0_ab, xb1,
                               xa0, ssa, cnta, root0_ba, bias0_ba, xa1);

    // 7. re-zero ss
    k_zero<<<((NA + NB) * DD + 255) / 256, 256>>>(ss, (NA + NB) * DD);

    // 8. conv layer 1
    k_conv2<<<2 * NBLK_C, 256, CONV_SMEM>>>(xa1, hab, wnab, src_ab, dst_ab, ssb,
                                            xb1, hba, wnba, src_ba, dst_ba, ssa);

    // 9. finalize layer 1
    k_finalize2<<<1564, 256>>>(xb1, ssb, cntb, root1_ab, bias1_ab, out + (size_t)NA * DD,
                               xa1, ssa, cnta, root1_ba, bias1_ba, out);
}

// round 15
// speedup vs baseline: 1.0420x; 1.0420x over previous
#include <cuda_runtime.h>
#include <cuda_fp16.h>
#include <cstdint>

#define NA 50000
#define NB 50000
#define DD 64
#define FEAT 16
#define EE 30000
#define EPAD 30208     // 118 * 256, padded M for 256-row conv tiles
#define NBLK_C 118     // conv M-tiles per edge type (256 edges each)
#define NCHUNK 65      // 64 weight chunks + 1 bias chunk
#define CHUNK_HALVES 4096   // 64 o-rows x 64 k, 8192 bytes
#define CHUNK_BYTES 8192

// conv dynamic smem layout
#define SM_H     0            // 256*72 halves = 36864 B
#define SM_BUF   36864        // 3 * 8192 B = 24576
#define SM_MBAR  61440        // 3 full + 3 empty mbarriers = 48 B
#define CONV_SMEM 61488

#define SXW 68   // padded fp32 row stride (64-wide tiles): 16B-aligned, conflict-free
#define SEW 20   // padded fp32 row stride (16-wide tiles)

#define PK_BLKS (2 * NCHUNK)          // 130 pack blocks
#define CNT_BLKS ((2 * EE + 255) / 256)  // 235 count blocks

// ---------------- scratch (static device globals; no allocs) ----------------
__device__ float  g_xa0[NA * DD];
__device__ float  g_xb0[NB * DD];
__device__ float  g_xa1[NA * DD];
__device__ float  g_xb1[NB * DD];
__device__ __half g_hab[EPAD * DD];      // edge-MLP hidden, fp16, zero-padded rows
__device__ __half g_hba[EPAD * DD];
__device__ __half g_wn_ab[NCHUNK * CHUNK_HALVES];  // chunk-major packed W2v, SW128-swizzled
__device__ __half g_wn_ba[NCHUNK * CHUNK_HALVES];
__device__ float  g_ss[(NA + NB) * DD];  // ssa = g_ss, ssb = g_ss + NA*DD
__device__ float  g_cnt[NA + NB];        // cnta = g_cnt, cntb = g_cnt + NA

// ---------------- helpers ----------------
__device__ __forceinline__ uint32_t smem_u32(const void* p) {
    uint32_t a;
    asm("{ .reg .u64 t; cvta.to.shared.u64 t, %1; cvt.u32.u64 %0, t; }" : "=r"(a) : "l"(p));
    return a;
}

__device__ __forceinline__ void ldsm_x4(uint32_t& r0, uint32_t& r1, uint32_t& r2, uint32_t& r3,
                                        uint32_t addr) {
    asm volatile("ldmatrix.sync.aligned.m8n8.x4.shared.b16 {%0,%1,%2,%3}, [%4];"
                 : "=r"(r0), "=r"(r1), "=r"(r2), "=r"(r3) : "r"(addr));
}

__device__ __forceinline__ void mma16816(float* d, const uint32_t* a, const uint32_t* b) {
    asm volatile(
        "mma.sync.aligned.m16n8k16.row.col.f32.f16.f16.f32 "
        "{%0,%1,%2,%3}, {%4,%5,%6,%7}, {%8,%9}, {%0,%1,%2,%3};"
        : "+f"(d[0]), "+f"(d[1]), "+f"(d[2]), "+f"(d[3])
        : "r"(a[0]), "r"(a[1]), "r"(a[2]), "r"(a[3]), "r"(b[0]), "r"(b[1]));
}

__device__ __forceinline__ uint32_t f2h2(float x, float y) {
    __half2 h = __floats2half2_rn(x, y);
    return *(uint32_t*)&h;
}

__device__ __forceinline__ uint32_t hmul2u(uint32_t a, uint32_t s) {
    __half2 r = __hmul2(*(__half2*)&a, *(__half2*)&s);
    return *(uint32_t*)&r;
}

__device__ __forceinline__ void mbar_wait(uint32_t mbar, uint32_t parity) {
    uint32_t done;
    asm volatile(
        "{\n\t.reg .pred p;\n\t"
        "mbarrier.try_wait.parity.shared.b64 p, [%1], %2;\n\t"
        "selp.b32 %0, 1, 0, p;\n\t}"
        : "=r"(done) : "r"(mbar), "r"(parity) : "memory");
    if (!done) {
        asm volatile(
            "{\n\t.reg .pred P1;\n\t"
            "WL_%=:\n\t"
            "mbarrier.try_wait.parity.shared.b64 P1, [%0], %1, 0x989680;\n\t"
            "@P1 bra.uni WD_%=;\n\t"
            "bra.uni WL_%=;\n\t"
            "WD_%=:\n\t}"
            :: "r"(mbar), "r"(parity) : "memory");
    }
}

// ---------------- utility kernels ----------------
__global__ void k_zero(float* __restrict__ p, int n) {
    int i = blockIdx.x * 256 + threadIdx.x;
    if (i < n) p[i] = 0.f;
}

// zero ss + cnt in one launch
__global__ void k_zero2(float* __restrict__ ss, float* __restrict__ cnt) {
    int i = blockIdx.x * 256 + threadIdx.x;
    const int SSN = (NA + NB) * DD;
    if (i < SSN) ss[i] = 0.f;
    else if (i < SSN + NA + NB) cnt[i - SSN] = 0.f;
}

// pack W2 + b2 (tiled transpose, blocks [0,130)) + degree counts (blocks [130,365))
__global__ void __launch_bounds__(256) k_packcnt(
    const float* __restrict__ W2a, const float* __restrict__ b2a, __half* __restrict__ WNa,
    const float* __restrict__ W2b, const float* __restrict__ b2b, __half* __restrict__ WNb,
    const int* __restrict__ dst_ab, const int* __restrict__ dst_ba,
    float* __restrict__ cnta, float* __restrict__ cntb)
{
    __shared__ float sT[64 * SXW];   // [ki][o], padded
    int bid = blockIdx.x;
    const int tid = threadIdx.x;

    if (bid >= PK_BLKS) {
        // ---- degree counts ----
        int i = (bid - PK_BLKS) * 256 + tid;
        if (i < EE) atomicAdd(&cntb[dst_ab[i]], 1.f);
        else if (i < 2 * EE) atomicAdd(&cnta[dst_ba[i - EE]], 1.f);
        return;
    }

    const float* W2; const float* b2; __half* WN;
    if (bid < NCHUNK) { W2 = W2a; b2 = b2a; WN = WNa; }
    else { bid -= NCHUNK; W2 = W2b; b2 = b2b; WN = WNb; }
    const int chunk = bid;
    const float* src = (chunk < 64) ? (W2 + (size_t)chunk * 4096) : b2;

#pragma unroll
    for (int j = 0; j < 4; j++) {
        int li = tid + 256 * j;
        int ki = li >> 4, o4 = (li & 15) * 4;
        float4 v = *(const float4*)(src + ki * 64 + o4);
        *(float4*)(sT + ki * SXW + o4) = v;
    }
    __syncthreads();

    __half* dst = WN + (size_t)chunk * CHUNK_HALVES;
#pragma unroll
    for (int j = 0; j < 8; j++) {
        int w = tid * 8 + j;
        int o = w >> 5, kp = w & 31;
        __half2 h = __floats2half2_rn(sT[(2 * kp) * SXW + o], sT[(2 * kp + 1) * SXW + o]);
        uint32_t boff = (uint32_t)(o * 128 + kp * 4);
        boff ^= (boff >> 3) & 0x70;
        *(__half2*)((char*)dst + boff) = h;
    }
}

// ---------------- merged node-linear + edge-MLP ----------------
__global__ void __launch_bounds__(256) k_ne(
    const float* __restrict__ emb_a, const int* __restrict__ x_a,
    const float* __restrict__ Wn_a, const float* __restrict__ bn_a, float* __restrict__ xa0,
    const float* __restrict__ emb_b, const int* __restrict__ x_b,
    const float* __restrict__ Wn_b, const float* __restrict__ bn_b, float* __restrict__ xb0,
    const float* __restrict__ ea_ab, const float* __restrict__ W1_ab,
    const float* __restrict__ b1_ab, __half* __restrict__ hab,
    const float* __restrict__ ea_ba, const float* __restrict__ W1_ba,
    const float* __restrict__ b1_ba, __half* __restrict__ hba)
{
    __shared__ __align__(16) float pool[8512];
    float* sW = pool;
    float* sB = pool + 4096;
    float* sX = pool + 4160;
    int bid = blockIdx.x;
    int tid = threadIdx.x;

    if (bid < 1564) {
        const float* X; const int* idx; const float* W; const float* b; float* Y; int N;
        if (bid < 782) { X = emb_a; idx = x_a; W = Wn_a; b = bn_a; Y = xa0; N = NA; }
        else { bid -= 782; X = emb_b; idx = x_b; W = Wn_b; b = bn_b; Y = xb0; N = NB; }
        for (int i = tid; i < 1024; i += 256)
            ((float4*)sW)[i] = ((const float4*)W)[i];
        if (tid < 64) sB[tid] = b[tid];
        int n0 = bid * 64;
        int r = tid >> 2, c0 = (tid & 3) * 16;
        int n = n0 + r;
        {
            float4* sxp = (float4*)(sX + r * SXW + c0);
            if (n < N) {
                int s = idx[n];
                const float4* xr = (const float4*)(X + (size_t)s * 64 + c0);
#pragma unroll
                for (int k = 0; k < 4; k++) sxp[k] = xr[k];
            } else {
                float4 z = {0.f, 0.f, 0.f, 0.f};
#pragma unroll
                for (int k = 0; k < 4; k++) sxp[k] = z;
            }
        }
        __syncthreads();
        int o0 = (tid & 3) * 16;
        float acc[16];
#pragma unroll
        for (int j = 0; j < 16; j++) acc[j] = sB[o0 + j];
        const float* sxr = sX + r * SXW;
#pragma unroll 8
        for (int d = 0; d < 64; d++) {
            float xv = sxr[d];
            const float4* wr = (const float4*)(sW + d * 64 + o0);
            float4 w0 = wr[0], w1 = wr[1], w2 = wr[2], w3 = wr[3];
            acc[0]  += xv * w0.x; acc[1]  += xv * w0.y; acc[2]  += xv * w0.z; acc[3]  += xv * w0.w;
            acc[4]  += xv * w1.x; acc[5]  += xv * w1.y; acc[6]  += xv * w1.z; acc[7]  += xv * w1.w;
            acc[8]  += xv * w2.x; acc[9]  += xv * w2.y; acc[10] += xv * w2.z; acc[11] += xv * w2.w;
            acc[12] += xv * w3.x; acc[13] += xv * w3.y; acc[14] += xv * w3.z; acc[15] += xv * w3.w;
        }
        if (n < N) {
            float4* yp = (float4*)(Y + (size_t)n * 64 + o0);
#pragma unroll
            for (int k = 0; k < 4; k++) {
                float4 v = {acc[4 * k], acc[4 * k + 1], acc[4 * k + 2], acc[4 * k + 3]};
                yp[k] = v;
            }
        }
    } else {
        bid -= 1564;
        const float* EA; const float* W1; const float* b1; __half* H;
        if (bid < 472) { EA = ea_ab; W1 = W1_ab; b1 = b1_ab; H = hab; }
        else { bid -= 472; EA = ea_ba; W1 = W1_ba; b1 = b1_ba; H = hba; }
        if (tid < 256) ((float4*)sW)[tid] = ((const float4*)W1)[tid];
        if (tid < 64) sB[tid] = b1[tid];
        int e0 = bid * 64;
        int r = tid >> 2, c0 = (tid & 3) * 4;
        int e = e0 + r;
        {
            float4* sxp = (float4*)(sX + r * SEW + c0);
            if (e < EE) {
                sxp[0] = *(const float4*)(EA + (size_t)e * 16 + c0);
            } else {
                float4 z = {0.f, 0.f, 0.f, 0.f};
                sxp[0] = z;
            }
        }
        __syncthreads();
        int o0 = (tid & 3) * 16;
        float acc[16];
#pragma unroll
        for (int j = 0; j < 16; j++) acc[j] = sB[o0 + j];
        const float* sxr = sX + r * SEW;
#pragma unroll
        for (int d = 0; d < 16; d++) {
            float xv = sxr[d];
            const float4* wr = (const float4*)(sW + d * 64 + o0);
            float4 w0 = wr[0], w1 = wr[1], w2 = wr[2], w3 = wr[3];
            acc[0]  += xv * w0.x; acc[1]  += xv * w0.y; acc[2]  += xv * w0.z; acc[3]  += xv * w0.w;
            acc[4]  += xv * w1.x; acc[5]  += xv * w1.y; acc[6]  += xv * w1.z; acc[7]  += xv * w1.w;
            acc[8]  += xv * w2.x; acc[9]  += xv * w2.y; acc[10] += xv * w2.z; acc[11] += xv * w2.w;
            acc[12] += xv * w3.x; acc[13] += xv * w3.y; acc[14] += xv * w3.z; acc[15] += xv * w3.w;
        }
        {
            __half2 h[8];
            if (e < EE) {
#pragma unroll
                for (int j = 0; j < 8; j++)
                    h[j] = __floats2half2_rn(fmaxf(acc[2 * j], 0.f), fmaxf(acc[2 * j + 1], 0.f));
            } else {
#pragma unroll
                for (int j = 0; j < 8; j++) h[j] = __floats2half2_rn(0.f, 0.f);
            }
            uint4* hp = (uint4*)(H + (size_t)e * 64 + o0);
            const uint4* hs = (const uint4*)h;
            hp[0] = hs[0]; hp[1] = hs[1];
        }
    }
}

// ---------------- fused conv (EXACT Round-13 configuration: 256 edges/CTA,
// 8 warps x 32 rows, 2 CTAs/SM, bulk-copy + decoupled mbarrier pipeline) -----
__global__ void __launch_bounds__(256, 2) k_conv2(
    const float* __restrict__ Xa, const __half* __restrict__ Ha,
    const __half* __restrict__ WNa, const int* __restrict__ SRCa,
    const int* __restrict__ DSTa, float* __restrict__ SSa,
    const float* __restrict__ Xb, const __half* __restrict__ Hb,
    const __half* __restrict__ WNb, const int* __restrict__ SRCb,
    const int* __restrict__ DSTb, float* __restrict__ SSb)
{
    extern __shared__ __align__(16) char dsm[];
    __half* sH = (__half*)(dsm + SM_H);             // 256 x 72 halves
    int bid = blockIdx.x;
    const float* X; const __half* H; const __half* WN;
    const int* SRC; const int* DST; float* SS;
    if (bid < NBLK_C) { X = Xa; H = Ha; WN = WNa; SRC = SRCa; DST = DSTa; SS = SSa; }
    else { bid -= NBLK_C; X = Xb; H = Hb; WN = WNb; SRC = SRCb; DST = DSTb; SS = SSb; }

    const int tid = threadIdx.x, lane = tid & 31, wid = tid >> 5;
    const int e0 = bid * 256;
    const uint32_t sBuf = smem_u32(dsm + SM_BUF);
    const uint32_t mfull = smem_u32(dsm + SM_MBAR);
    const uint32_t mempty = mfull + 24;

    if (tid == 0) {
#pragma unroll
        for (int b = 0; b < 3; b++) {
            asm volatile("mbarrier.init.shared.b64 [%0], %1;" :: "r"(mfull + b * 8), "r"(1u) : "memory");
            asm volatile("mbarrier.init.shared.b64 [%0], %1;" :: "r"(mempty + b * 8), "r"(8u) : "memory");
        }
    }

    // stage H tile: 256 rows x 64 halves -> padded stride 72
    {
        const uint4* hg = (const uint4*)(H + (size_t)e0 * 64);
#pragma unroll
        for (int i = 0; i < 8; i++) {
            int idx = tid + 256 * i;            // 2048 x 16B
            int row = idx >> 3, seg = idx & 7;
            *(uint4*)((char*)sH + (row * 72 + seg * 8) * 2) = hg[idx];
        }
    }
    __syncthreads();   // mbar init + sH visible

#define BULK_ISSUE(c) do {                                                        \
        uint32_t mb_ = mfull + ((c) % 3) * 8;                                     \
        asm volatile("mbarrier.arrive.expect_tx.shared.b64 _, [%0], %1;"          \
                     :: "r"(mb_), "r"((uint32_t)CHUNK_BYTES) : "memory");         \
        asm volatile("cp.async.bulk.shared::cta.global.mbarrier::complete_tx::bytes " \
                     "[%0], [%1], %2, [%3];"                                      \
                     :: "r"(sBuf + ((c) % 3) * CHUNK_BYTES),                      \
                        "l"(WN + (size_t)(c) * CHUNK_HALVES),                     \
                        "r"((uint32_t)CHUNK_BYTES), "r"(mb_) : "memory");         \
    } while (0)

    if (tid == 0) { BULK_ISSUE(0); BULK_ISSUE(1); }

    // 4 row slots per thread: rbase+0, +8 (mt=0) and +16, +24 (mt=1)
    const int rbase = wid * 32 + (lane >> 2);
    const int m2 = (lane & 3) * 2;
    int eg[4], sidx[4];
#pragma unroll
    for (int q = 0; q < 4; q++) {
        eg[q] = e0 + rbase + q * 8;
        sidx[q] = (eg[q] < EE) ? SRC[eg[q]] : 0;
    }

    // x fragments (fp16, register-resident for whole K loop)
    uint32_t xF[2][4][4];
#pragma unroll
    for (int mt = 0; mt < 2; mt++) {
        const float* xp0 = X + (size_t)sidx[2 * mt] * 64;
        const float* xp1 = X + (size_t)sidx[2 * mt + 1] * 64;
#pragma unroll
        for (int ks = 0; ks < 4; ks++) {
            float2 v;
            v = *(const float2*)(xp0 + ks * 16 + m2);     xF[mt][ks][0] = f2h2(v.x, v.y);
            v = *(const float2*)(xp1 + ks * 16 + m2);     xF[mt][ks][1] = f2h2(v.x, v.y);
            v = *(const float2*)(xp0 + ks * 16 + m2 + 8); xF[mt][ks][2] = f2h2(v.x, v.y);
            v = *(const float2*)(xp1 + ks * 16 + m2 + 8); xF[mt][ks][3] = f2h2(v.x, v.y);
        }
    }

    float acc[2][8][4];
#pragma unroll
    for (int mt = 0; mt < 2; mt++)
#pragma unroll
        for (int j = 0; j < 8; j++)
#pragma unroll
            for (int q = 0; q < 4; q++) acc[mt][j][q] = 0.f;

    for (int kc = 0; kc < NCHUNK; kc++) {
        if (tid == 0) {
            if (kc == 0) {
                BULK_ISSUE(2);
            } else if (kc + 2 < NCHUNK) {
                mbar_wait(mempty + ((kc - 1) % 3) * 8, (uint32_t)(((kc - 1) / 3) & 1));
                BULK_ISSUE(kc + 2);
            }
        }
        mbar_wait(mfull + (kc % 3) * 8, (uint32_t)((kc / 3) & 1));

        uint32_t sc[4];
        if (kc < 64) {
#pragma unroll
            for (int q = 0; q < 4; q++) {
                __half2 t = __half2half2(sH[(rbase + q * 8) * 72 + kc]);
                sc[q] = *(uint32_t*)&t;
            }
        } else {
            __half2 one = __floats2half2_rn(1.f, 1.f);
            sc[0] = sc[1] = sc[2] = sc[3] = *(uint32_t*)&one;
        }

        const uint32_t bufb = sBuf + (kc % 3) * CHUNK_BYTES;
#pragma unroll
        for (int ks = 0; ks < 4; ks++) {
            uint32_t aR0[4], aR1[4];
            aR0[0] = hmul2u(xF[0][ks][0], sc[0]);
            aR0[1] = hmul2u(xF[0][ks][1], sc[1]);
            aR0[2] = hmul2u(xF[0][ks][2], sc[0]);
            aR0[3] = hmul2u(xF[0][ks][3], sc[1]);
            aR1[0] = hmul2u(xF[1][ks][0], sc[2]);
            aR1[1] = hmul2u(xF[1][ks][1], sc[3]);
            aR1[2] = hmul2u(xF[1][ks][2], sc[2]);
            aR1[3] = hmul2u(xF[1][ks][3], sc[3]);
#pragma unroll
            for (int p = 0; p < 4; p++) {
                int r = p * 16 + (lane & 15);
                uint32_t off = (uint32_t)(r * 128 + (ks * 16 + ((lane >> 4) << 3)) * 2);
                off ^= (off >> 3) & 0x70;
                uint32_t b0[2], b1[2];
                ldsm_x4(b0[0], b1[0], b0[1], b1[1], bufb + off);
                mma16816(acc[0][2 * p],     aR0, b0);
                mma16816(acc[0][2 * p + 1], aR0, b1);
                mma16816(acc[1][2 * p],     aR1, b0);
                mma16816(acc[1][2 * p + 1], aR1, b1);
            }
        }
        if (lane == 0)
            asm volatile("mbarrier.arrive.shared.b64 _, [%0];"
                         :: "r"(mempty + (kc % 3) * 8) : "memory");
    }
#undef BULK_ISSUE

    int dd[4];
#pragma unroll
    for (int q = 0; q < 4; q++) dd[q] = (eg[q] < EE) ? DST[eg[q]] : -1;
#pragma unroll
    for (int mt = 0; mt < 2; mt++) {
#pragma unroll
        for (int j = 0; j < 8; j++) {
            int c = j * 8 + m2;
            if (dd[2 * mt] >= 0) {
                atomicAdd(&SS[(size_t)dd[2 * mt] * 64 + c],     acc[mt][j][0]);
                atomicAdd(&SS[(size_t)dd[2 * mt] * 64 + c + 1], acc[mt][j][1]);
            }
            if (dd[2 * mt + 1] >= 0) {
                atomicAdd(&SS[(size_t)dd[2 * mt + 1] * 64 + c],     acc[mt][j][2]);
                atomicAdd(&SS[(size_t)dd[2 * mt + 1] * 64 + c + 1], acc[mt][j][3]);
            }
        }
    }
}

// Y[n,:] = relu( SS[n,:]/max(cnt,1) + Xprev[n,:] @ root + bias )  (UNCHANGED)
__global__ void __launch_bounds__(256) k_finalize2(
    const float* __restrict__ Xb_, const float* __restrict__ SSb_,
    const float* __restrict__ CNTb_, const float* __restrict__ Wab,
    const float* __restrict__ bab, float* __restrict__ Yb_,
    const float* __restrict__ Xa_, const float* __restrict__ SSa_,
    const float* __restrict__ CNTa_, const float* __restrict__ Wba,
    const float* __restrict__ bba, float* __restrict__ Ya_)
{
    __shared__ float sW[64 * 64];
    __shared__ float sB[64];
    __shared__ float sX[64 * SXW];
    int bid = blockIdx.x;
    const float* Xp; const float* SS; const float* CNT; const float* W; const float* b;
    float* Y; int N;
    if (bid < 782) { Xp = Xb_; SS = SSb_; CNT = CNTb_; W = Wab; b = bab; Y = Yb_; N = NB; }
    else { bid -= 782; Xp = Xa_; SS = SSa_; CNT = CNTa_; W = Wba; b = bba; Y = Ya_; N = NA; }
    int tid = threadIdx.x;
    for (int i = tid; i < 1024; i += 256)
        ((float4*)sW)[i] = ((const float4*)W)[i];
    if (tid < 64) sB[tid] = b[tid];
    int n0 = bid * 64;
    int r = tid >> 2, c0 = (tid & 3) * 16;
    int n = n0 + r;
    {
        float4* sxp = (float4*)(sX + r * SXW + c0);
        if (n < N) {
            const float4* xr = (const float4*)(Xp + (size_t)n * 64 + c0);
#pragma unroll
            for (int k = 0; k < 4; k++) sxp[k] = xr[k];
        } else {
            float4 z = {0.f, 0.f, 0.f, 0.f};
#pragma unroll
            for (int k = 0; k < 4; k++) sxp[k] = z;
        }
    }
    __syncthreads();
    int o0 = (tid & 3) * 16;
    float acc[16];
#pragma unroll
    for (int j = 0; j < 16; j++) acc[j] = sB[o0 + j];
    const float* sxr = sX + r * SXW;
#pragma unroll 8
    for (int d = 0; d < 64; d++) {
        float xv = sxr[d];
        const float4* wr = (const float4*)(sW + d * 64 + o0);
        float4 w0 = wr[0], w1 = wr[1], w2 = wr[2], w3 = wr[3];
        acc[0]  += xv * w0.x; acc[1]  += xv * w0.y; acc[2]  += xv * w0.z; acc[3]  += xv * w0.w;
        acc[4]  += xv * w1.x; acc[5]  += xv * w1.y; acc[6]  += xv * w1.z; acc[7]  += xv * w1.w;
        acc[8]  += xv * w2.x; acc[9]  += xv * w2.y; acc[10] += xv * w2.z; acc[11] += xv * w2.w;
        acc[12] += xv * w3.x; acc[13] += xv * w3.y; acc[14] += xv * w3.z; acc[15] += xv * w3.w;
    }
    if (n < N) {
        float ic = 1.f / fmaxf(CNT[n], 1.f);
        const float4* sp = (const float4*)(SS + (size_t)n * 64 + o0);
        float4* yp = (float4*)(Y + (size_t)n * 64 + o0);
#pragma unroll
        for (int k = 0; k < 4; k++) {
            float4 s = sp[k];
            float4 v;
            v.x = fmaxf(acc[4 * k + 0] + s.x * ic, 0.f);
            v.y = fmaxf(acc[4 * k + 1] + s.y * ic, 0.f);
            v.z = fmaxf(acc[4 * k + 2] + s.z * ic, 0.f);
            v.w = fmaxf(acc[4 * k + 3] + s.w * ic, 0.f);
            yp[k] = v;
        }
    }
}

// ---------------- launcher ----------------
static void* sym(const void* s) {
    void* p = nullptr;
    cudaGetSymbolAddress(&p, s);
    return p;
}

extern "C" void kernel_launch(void* const* d_in, const int* in_sizes, int n_in,
                              void* d_out, int out_size)
{
    const int*   x_a      = (const int*)d_in[0];
    const int*   x_b      = (const int*)d_in[1];
    const int*   ei_ab    = (const int*)d_in[2];   // [2,E]
    const int*   ei_ba    = (const int*)d_in[3];
    const float* ea_ab    = (const float*)d_in[4];
    const float* ea_ba    = (const float*)d_in[5];
    const float* emb_a    = (const float*)d_in[6];
    const float* emb_b    = (const float*)d_in[7];
    const float* Wn_a     = (const float*)d_in[8];
    const float* bn_a     = (const float*)d_in[9];
    const float* Wn_b     = (const float*)d_in[10];
    const float* bn_b     = (const float*)d_in[11];
    const float* W1_ab    = (const float*)d_in[12];
    const float* b1_ab    = (const float*)d_in[13];
    const float* W2_ab    = (const float*)d_in[14];
    const float* b2_ab    = (const float*)d_in[15];
    const float* W1_ba    = (const float*)d_in[16];
    const float* b1_ba    = (const float*)d_in[17];
    const float* W2_ba    = (const float*)d_in[18];
    const float* b2_ba    = (const float*)d_in[19];
    const float* root0_ab = (const float*)d_in[20];
    const float* bias0_ab = (const float*)d_in[21];
    const float* root0_ba = (const float*)d_in[22];
    const float* bias0_ba = (const float*)d_in[23];
    const float* root1_ab = (const float*)d_in[24];
    const float* bias1_ab = (const float*)d_in[25];
    const float* root1_ba = (const float*)d_in[26];
    const float* bias1_ba = (const float*)d_in[27];

    float*  xa0 = (float*)sym(g_xa0);
    float*  xb0 = (float*)sym(g_xb0);
    float*  xa1 = (float*)sym(g_xa1);
    float*  xb1 = (float*)sym(g_xb1);
    __half* hab = (__half*)sym(g_hab);
    __half* hba = (__half*)sym(g_hba);
    __half* wnab = (__half*)sym(g_wn_ab);
    __half* wnba = (__half*)sym(g_wn_ba);
    float*  ss  = (float*)sym(g_ss);
    float*  cnt = (float*)sym(g_cnt);
    float*  ssa = ss;
    float*  ssb = ss + (size_t)NA * DD;
    float*  cnta = cnt;
    float*  cntb = cnt + NA;

    const int* src_ab = ei_ab;
    const int* dst_ab = ei_ab + EE;
    const int* src_ba = ei_ba;
    const int* dst_ba = ei_ba + EE;

    float* out = (float*)d_out;

    cudaFuncSetAttribute(k_conv2, cudaFuncAttributeMaxDynamicSharedMemorySize, CONV_SMEM);

    // 1. zero ss + cnt
    const int ZN = (NA + NB) * DD + (NA + NB);
    k_zero2<<<(ZN + 255) / 256, 256>>>(ss, cnt);

    // 2. pack W2+b2 + degree counts (merged, independent)
    k_packcnt<<<PK_BLKS + CNT_BLKS, 256>>>(W2_ab, b2_ab, wnab, W2_ba, b2_ba, wnba,
                                           dst_ab, dst_ba, cnta, cntb);

    // 3. node features + edge MLP (merged)
    k_ne<<<2508, 256>>>(emb_a, x_a, Wn_a, bn_a, xa0,
                        emb_b, x_b, Wn_b, bn_b, xb0,
                        ea_ab, W1_ab, b1_ab, hab,
                        ea_ba, W1_ba, b1_ba, hba);

    // 4. conv layer 0  (<- ncu profiles this launch)
    k_conv2<<<2 * NBLK_C, 256, CONV_SMEM>>>(xa0, hab, wnab, src_ab, dst_ab, ssb,
                                            xb0, hba, wnba, src_ba, dst_ba, ssa);

    // 5. finalize layer 0
    k_finalize2<<<1564, 256>>>(xb0, ssb, cntb, root0_ab, bias0_ab, xb1,
                               xa0, ssa, cnta, root0_ba, bias0_ba, xa1);

    // 6. re-zero ss
    k_zero<<<((NA + NB) * DD + 255) / 256, 256>>>(ss, (NA + NB) * DD);

    // 7. conv layer 1
    k_conv2<<<2 * NBLK_C, 256, CONV_SMEM>>>(xa1, hab, wnab, src_ab, dst_ab, ssb,
                                            xb1, hba, wnba, src_ba, dst_ba, ssa);

    // 8. finalize layer 1
    k_finalize2<<<1564, 256>>>(xb1, ssb, cntb, root1_ab, bias1_ab, out + (size_t)NA * DD,
                               xa1, ssa, cnta, root1_ba, bias1_ba, out);
}

// round 16
// speedup vs baseline: 1.3179x; 1.2648x over previous
#include <cuda_runtime.h>
#include <cuda_fp16.h>
#include <cstdint>

#define NA 50000
#define NB 50000
#define DD 64
#define FEAT 16
#define EE 30000
#define EPAD 30208     // 118 * 256, padded M for 256-row conv tiles
#define NBLK_C 118     // conv M-tiles per edge type (256 edges each)
#define NCHUNK 65
#define CHUNK_HALVES 4096
#define CHUNK_BYTES 8192

// conv dynamic smem layout
#define SM_H     0
#define SM_BUF   36864
#define SM_MBAR  61440
#define CONV_SMEM 61488

#define SXW 68   // padded fp32 row stride (64-wide tiles)
#define SEW 20   // padded fp32 row stride (16-wide tiles)

#define PK_BLKS (2 * NCHUNK)             // 130 pack blocks
#define CNT_BLKS ((2 * EE + 255) / 256)  // 235 count blocks

#define NTILE 391                        // ceil(50000/128)
// ne/finalize dynamic smem: sW(4096) + sB(64) + sX(128*68) floats
#define NF_SMEM ((4096 + 64 + 128 * SXW) * 4)

// ---------------- scratch ----------------
__device__ float  g_xa0[NA * DD];
__device__ float  g_xb0[NB * DD];
__device__ float  g_xa1[NA * DD];
__device__ float  g_xb1[NB * DD];
__device__ __half g_hab[EPAD * DD];
__device__ __half g_hba[EPAD * DD];
__device__ __half g_wn_ab[NCHUNK * CHUNK_HALVES];
__device__ __half g_wn_ba[NCHUNK * CHUNK_HALVES];
__device__ float  g_ss[(NA + NB) * DD];
__device__ float  g_cnt[NA + NB];

// ---------------- helpers ----------------
__device__ __forceinline__ uint32_t smem_u32(const void* p) {
    uint32_t a;
    asm("{ .reg .u64 t; cvta.to.shared.u64 t, %1; cvt.u32.u64 %0, t; }" : "=r"(a) : "l"(p));
    return a;
}

__device__ __forceinline__ void ldsm_x4(uint32_t& r0, uint32_t& r1, uint32_t& r2, uint32_t& r3,
                                        uint32_t addr) {
    asm volatile("ldmatrix.sync.aligned.m8n8.x4.shared.b16 {%0,%1,%2,%3}, [%4];"
                 : "=r"(r0), "=r"(r1), "=r"(r2), "=r"(r3) : "r"(addr));
}

__device__ __forceinline__ void mma16816(float* d, const uint32_t* a, const uint32_t* b) {
    asm volatile(
        "mma.sync.aligned.m16n8k16.row.col.f32.f16.f16.f32 "
        "{%0,%1,%2,%3}, {%4,%5,%6,%7}, {%8,%9}, {%0,%1,%2,%3};"
        : "+f"(d[0]), "+f"(d[1]), "+f"(d[2]), "+f"(d[3])
        : "r"(a[0]), "r"(a[1]), "r"(a[2]), "r"(a[3]), "r"(b[0]), "r"(b[1]));
}

__device__ __forceinline__ uint32_t f2h2(float x, float y) {
    __half2 h = __floats2half2_rn(x, y);
    return *(uint32_t*)&h;
}

__device__ __forceinline__ uint32_t hmul2u(uint32_t a, uint32_t s) {
    __half2 r = __hmul2(*(__half2*)&a, *(__half2*)&s);
    return *(uint32_t*)&r;
}

__device__ __forceinline__ void mbar_wait(uint32_t mbar, uint32_t parity) {
    uint32_t done;
    asm volatile(
        "{\n\t.reg .pred p;\n\t"
        "mbarrier.try_wait.parity.shared.b64 p, [%1], %2;\n\t"
        "selp.b32 %0, 1, 0, p;\n\t}"
        : "=r"(done) : "r"(mbar), "r"(parity) : "memory");
    if (!done) {
        asm volatile(
            "{\n\t.reg .pred P1;\n\t"
            "WL_%=:\n\t"
            "mbarrier.try_wait.parity.shared.b64 P1, [%0], %1, 0x989680;\n\t"
            "@P1 bra.uni WD_%=;\n\t"
            "bra.uni WL_%=;\n\t"
            "WD_%=:\n\t}"
            :: "r"(mbar), "r"(parity) : "memory");
    }
}

// ---------------- utility kernels ----------------
__global__ void k_zero(float* __restrict__ p, int n) {
    int i = blockIdx.x * 256 + threadIdx.x;
    if (i < n) p[i] = 0.f;
}

__global__ void k_zero2(float* __restrict__ ss, float* __restrict__ cnt) {
    int i = blockIdx.x * 256 + threadIdx.x;
    const int SSN = (NA + NB) * DD;
    if (i < SSN) ss[i] = 0.f;
    else if (i < SSN + NA + NB) cnt[i - SSN] = 0.f;
}

// pack W2+b2 (tiled transpose, blocks [0,130)) + degree counts (blocks [130,365))
__global__ void __launch_bounds__(256) k_packcnt(
    const float* __restrict__ W2a, const float* __restrict__ b2a, __half* __restrict__ WNa,
    const float* __restrict__ W2b, const float* __restrict__ b2b, __half* __restrict__ WNb,
    const int* __restrict__ dst_ab, const int* __restrict__ dst_ba,
    float* __restrict__ cnta, float* __restrict__ cntb)
{
    __shared__ float sT[64 * SXW];
    int bid = blockIdx.x;
    const int tid = threadIdx.x;

    if (bid >= PK_BLKS) {
        int i = (bid - PK_BLKS) * 256 + tid;
        if (i < EE) atomicAdd(&cntb[dst_ab[i]], 1.f);
        else if (i < 2 * EE) atomicAdd(&cnta[dst_ba[i - EE]], 1.f);
        return;
    }

    const float* W2; const float* b2; __half* WN;
    if (bid < NCHUNK) { W2 = W2a; b2 = b2a; WN = WNa; }
    else { bid -= NCHUNK; W2 = W2b; b2 = b2b; WN = WNb; }
    const int chunk = bid;
    const float* src = (chunk < 64) ? (W2 + (size_t)chunk * 4096) : b2;

#pragma unroll
    for (int j = 0; j < 4; j++) {
        int li = tid + 256 * j;
        int ki = li >> 4, o4 = (li & 15) * 4;
        float4 v = *(const float4*)(src + ki * 64 + o4);
        *(float4*)(sT + ki * SXW + o4) = v;
    }
    __syncthreads();

    __half* dst = WN + (size_t)chunk * CHUNK_HALVES;
#pragma unroll
    for (int j = 0; j < 8; j++) {
        int w = tid * 8 + j;
        int o = w >> 5, kp = w & 31;
        __half2 h = __floats2half2_rn(sT[(2 * kp) * SXW + o], sT[(2 * kp + 1) * SXW + o]);
        uint32_t boff = (uint32_t)(o * 128 + kp * 4);
        boff ^= (boff >> 3) & 0x70;
        *(__half2*)((char*)dst + boff) = h;
    }
}

// ---------------- merged node-linear (128-row tiles, 2 rows/thread) + edge-MLP
// blocks [0,782): node linear (391 per type); blocks [782,1726): edge MLP.
__global__ void __launch_bounds__(256) k_ne(
    const float* __restrict__ emb_a, const int* __restrict__ x_a,
    const float* __restrict__ Wn_a, const float* __restrict__ bn_a, float* __restrict__ xa0,
    const float* __restrict__ emb_b, const int* __restrict__ x_b,
    const float* __restrict__ Wn_b, const float* __restrict__ bn_b, float* __restrict__ xb0,
    const float* __restrict__ ea_ab, const float* __restrict__ W1_ab,
    const float* __restrict__ b1_ab, __half* __restrict__ hab,
    const float* __restrict__ ea_ba, const float* __restrict__ W1_ba,
    const float* __restrict__ b1_ba, __half* __restrict__ hba)
{
    extern __shared__ __align__(16) float pool[];
    float* sW = pool;
    float* sB = pool + 4096;
    float* sX = pool + 4160;
    int bid = blockIdx.x;
    int tid = threadIdx.x;

    if (bid < 2 * NTILE) {
        // ---- node linear: 128 rows/block, thread computes rows r and r+64 ----
        const float* X; const int* idx; const float* W; const float* b; float* Y; int N;
        if (bid < NTILE) { X = emb_a; idx = x_a; W = Wn_a; b = bn_a; Y = xa0; N = NA; }
        else { bid -= NTILE; X = emb_b; idx = x_b; W = Wn_b; b = bn_b; Y = xb0; N = NB; }
        for (int i = tid; i < 1024; i += 256)
            ((float4*)sW)[i] = ((const float4*)W)[i];
        if (tid < 64) sB[tid] = b[tid];
        int n0 = bid * 128;
        int r = tid >> 2, c0 = (tid & 3) * 16;
        int nr0 = n0 + r, nr1 = n0 + r + 64;
#pragma unroll
        for (int h = 0; h < 2; h++) {
            int n = h ? nr1 : nr0;
            int rr = h ? r + 64 : r;
            float4* sxp = (float4*)(sX + rr * SXW + c0);
            if (n < N) {
                int s = idx[n];
                const float4* xr = (const float4*)(X + (size_t)s * 64 + c0);
#pragma unroll
                for (int k = 0; k < 4; k++) sxp[k] = xr[k];
            } else {
                float4 z = {0.f, 0.f, 0.f, 0.f};
#pragma unroll
                for (int k = 0; k < 4; k++) sxp[k] = z;
            }
        }
        __syncthreads();
        int o0 = (tid & 3) * 16;
        float acc0[16], acc1[16];
#pragma unroll
        for (int j = 0; j < 16; j++) { acc0[j] = sB[o0 + j]; acc1[j] = sB[o0 + j]; }
        const float* sx0 = sX + r * SXW;
        const float* sx1 = sX + (r + 64) * SXW;
#pragma unroll 8
        for (int d = 0; d < 64; d++) {
            float xv0 = sx0[d], xv1 = sx1[d];
            const float4* wr = (const float4*)(sW + d * 64 + o0);
            float4 w0 = wr[0], w1 = wr[1], w2 = wr[2], w3 = wr[3];
            acc0[0]  += xv0 * w0.x; acc0[1]  += xv0 * w0.y; acc0[2]  += xv0 * w0.z; acc0[3]  += xv0 * w0.w;
            acc0[4]  += xv0 * w1.x; acc0[5]  += xv0 * w1.y; acc0[6]  += xv0 * w1.z; acc0[7]  += xv0 * w1.w;
            acc0[8]  += xv0 * w2.x; acc0[9]  += xv0 * w2.y; acc0[10] += xv0 * w2.z; acc0[11] += xv0 * w2.w;
            acc0[12] += xv0 * w3.x; acc0[13] += xv0 * w3.y; acc0[14] += xv0 * w3.z; acc0[15] += xv0 * w3.w;
            acc1[0]  += xv1 * w0.x; acc1[1]  += xv1 * w0.y; acc1[2]  += xv1 * w0.z; acc1[3]  += xv1 * w0.w;
            acc1[4]  += xv1 * w1.x; acc1[5]  += xv1 * w1.y; acc1[6]  += xv1 * w1.z; acc1[7]  += xv1 * w1.w;
            acc1[8]  += xv1 * w2.x; acc1[9]  += xv1 * w2.y; acc1[10] += xv1 * w2.z; acc1[11] += xv1 * w2.w;
            acc1[12] += xv1 * w3.x; acc1[13] += xv1 * w3.y; acc1[14] += xv1 * w3.z; acc1[15] += xv1 * w3.w;
        }
        if (nr0 < N) {
            float4* yp = (float4*)(Y + (size_t)nr0 * 64 + o0);
#pragma unroll
            for (int k = 0; k < 4; k++) {
                float4 v = {acc0[4 * k], acc0[4 * k + 1], acc0[4 * k + 2], acc0[4 * k + 3]};
                yp[k] = v;
            }
        }
        if (nr1 < N) {
            float4* yp = (float4*)(Y + (size_t)nr1 * 64 + o0);
#pragma unroll
            for (int k = 0; k < 4; k++) {
                float4 v = {acc1[4 * k], acc1[4 * k + 1], acc1[4 * k + 2], acc1[4 * k + 3]};
                yp[k] = v;
            }
        }
    } else {
        // ---- edge MLP (unchanged body) ----
        bid -= 2 * NTILE;
        const float* EA; const float* W1; const float* b1; __half* H;
        if (bid < 472) { EA = ea_ab; W1 = W1_ab; b1 = b1_ab; H = hab; }
        else { bid -= 472; EA = ea_ba; W1 = W1_ba; b1 = b1_ba; H = hba; }
        if (tid < 256) ((float4*)sW)[tid] = ((const float4*)W1)[tid];
        if (tid < 64) sB[tid] = b1[tid];
        int e0 = bid * 64;
        int r = tid >> 2, c0 = (tid & 3) * 4;
        int e = e0 + r;
        {
            float4* sxp = (float4*)(sX + r * SEW + c0);
            if (e < EE) {
                sxp[0] = *(const float4*)(EA + (size_t)e * 16 + c0);
            } else {
                float4 z = {0.f, 0.f, 0.f, 0.f};
                sxp[0] = z;
            }
        }
        __syncthreads();
        int o0 = (tid & 3) * 16;
        float acc[16];
#pragma unroll
        for (int j = 0; j < 16; j++) acc[j] = sB[o0 + j];
        const float* sxr = sX + r * SEW;
#pragma unroll
        for (int d = 0; d < 16; d++) {
            float xv = sxr[d];
            const float4* wr = (const float4*)(sW + d * 64 + o0);
            float4 w0 = wr[0], w1 = wr[1], w2 = wr[2], w3 = wr[3];
            acc[0]  += xv * w0.x; acc[1]  += xv * w0.y; acc[2]  += xv * w0.z; acc[3]  += xv * w0.w;
            acc[4]  += xv * w1.x; acc[5]  += xv * w1.y; acc[6]  += xv * w1.z; acc[7]  += xv * w1.w;
            acc[8]  += xv * w2.x; acc[9]  += xv * w2.y; acc[10] += xv * w2.z; acc[11] += xv * w2.w;
            acc[12] += xv * w3.x; acc[13] += xv * w3.y; acc[14] += xv * w3.z; acc[15] += xv * w3.w;
        }
        {
            __half2 h[8];
            if (e < EE) {
#pragma unroll
                for (int j = 0; j < 8; j++)
                    h[j] = __floats2half2_rn(fmaxf(acc[2 * j], 0.f), fmaxf(acc[2 * j + 1], 0.f));
            } else {
#pragma unroll
                for (int j = 0; j < 8; j++) h[j] = __floats2half2_rn(0.f, 0.f);
            }
            uint4* hp = (uint4*)(H + (size_t)e * 64 + o0);
            const uint4* hs = (const uint4*)h;
            hp[0] = hs[0]; hp[1] = hs[1];
        }
    }
}

// ---------------- fused conv (EXACT R13/R15 configuration) ----------------
__global__ void __launch_bounds__(256, 2) k_conv2(
    const float* __restrict__ Xa, const __half* __restrict__ Ha,
    const __half* __restrict__ WNa, const int* __restrict__ SRCa,
    const int* __restrict__ DSTa, float* __restrict__ SSa,
    const float* __restrict__ Xb, const __half* __restrict__ Hb,
    const __half* __restrict__ WNb, const int* __restrict__ SRCb,
    const int* __restrict__ DSTb, float* __restrict__ SSb)
{
    extern __shared__ __align__(16) char dsm[];
    __half* sH = (__half*)(dsm + SM_H);
    int bid = blockIdx.x;
    const float* X; const __half* H; const __half* WN;
    const int* SRC; const int* DST; float* SS;
    if (bid < NBLK_C) { X = Xa; H = Ha; WN = WNa; SRC = SRCa; DST = DSTa; SS = SSa; }
    else { bid -= NBLK_C; X = Xb; H = Hb; WN = WNb; SRC = SRCb; DST = DSTb; SS = SSb; }

    const int tid = threadIdx.x, lane = tid & 31, wid = tid >> 5;
    const int e0 = bid * 256;
    const uint32_t sBuf = smem_u32(dsm + SM_BUF);
    const uint32_t mfull = smem_u32(dsm + SM_MBAR);
    const uint32_t mempty = mfull + 24;

    if (tid == 0) {
#pragma unroll
        for (int b = 0; b < 3; b++) {
            asm volatile("mbarrier.init.shared.b64 [%0], %1;" :: "r"(mfull + b * 8), "r"(1u) : "memory");
            asm volatile("mbarrier.init.shared.b64 [%0], %1;" :: "r"(mempty + b * 8), "r"(8u) : "memory");
        }
    }

    {
        const uint4* hg = (const uint4*)(H + (size_t)e0 * 64);
#pragma unroll
        for (int i = 0; i < 8; i++) {
            int idx = tid + 256 * i;
            int row = idx >> 3, seg = idx & 7;
            *(uint4*)((char*)sH + (row * 72 + seg * 8) * 2) = hg[idx];
        }
    }
    __syncthreads();

#define BULK_ISSUE(c) do {                                                        \
        uint32_t mb_ = mfull + ((c) % 3) * 8;                                     \
        asm volatile("mbarrier.arrive.expect_tx.shared.b64 _, [%0], %1;"          \
                     :: "r"(mb_), "r"((uint32_t)CHUNK_BYTES) : "memory");         \
        asm volatile("cp.async.bulk.shared::cta.global.mbarrier::complete_tx::bytes " \
                     "[%0], [%1], %2, [%3];"                                      \
                     :: "r"(sBuf + ((c) % 3) * CHUNK_BYTES),                      \
                        "l"(WN + (size_t)(c) * CHUNK_HALVES),                     \
                        "r"((uint32_t)CHUNK_BYTES), "r"(mb_) : "memory");         \
    } while (0)

    if (tid == 0) { BULK_ISSUE(0); BULK_ISSUE(1); }

    const int rbase = wid * 32 + (lane >> 2);
    const int m2 = (lane & 3) * 2;
    int eg[4], sidx[4];
#pragma unroll
    for (int q = 0; q < 4; q++) {
        eg[q] = e0 + rbase + q * 8;
        sidx[q] = (eg[q] < EE) ? SRC[eg[q]] : 0;
    }

    uint32_t xF[2][4][4];
#pragma unroll
    for (int mt = 0; mt < 2; mt++) {
        const float* xp0 = X + (size_t)sidx[2 * mt] * 64;
        const float* xp1 = X + (size_t)sidx[2 * mt + 1] * 64;
#pragma unroll
        for (int ks = 0; ks < 4; ks++) {
            float2 v;
            v = *(const float2*)(xp0 + ks * 16 + m2);     xF[mt][ks][0] = f2h2(v.x, v.y);
            v = *(const float2*)(xp1 + ks * 16 + m2);     xF[mt][ks][1] = f2h2(v.x, v.y);
            v = *(const float2*)(xp0 + ks * 16 + m2 + 8); xF[mt][ks][2] = f2h2(v.x, v.y);
            v = *(const float2*)(xp1 + ks * 16 + m2 + 8); xF[mt][ks][3] = f2h2(v.x, v.y);
        }
    }

    float acc[2][8][4];
#pragma unroll
    for (int mt = 0; mt < 2; mt++)
#pragma unroll
        for (int j = 0; j < 8; j++)
#pragma unroll
            for (int q = 0; q < 4; q++) acc[mt][j][q] = 0.f;

    for (int kc = 0; kc < NCHUNK; kc++) {
        if (tid == 0) {
            if (kc == 0) {
                BULK_ISSUE(2);
            } else if (kc + 2 < NCHUNK) {
                mbar_wait(mempty + ((kc - 1) % 3) * 8, (uint32_t)(((kc - 1) / 3) & 1));
                BULK_ISSUE(kc + 2);
            }
        }
        mbar_wait(mfull + (kc % 3) * 8, (uint32_t)((kc / 3) & 1));

        uint32_t sc[4];
        if (kc < 64) {
#pragma unroll
            for (int q = 0; q < 4; q++) {
                __half2 t = __half2half2(sH[(rbase + q * 8) * 72 + kc]);
                sc[q] = *(uint32_t*)&t;
            }
        } else {
            __half2 one = __floats2half2_rn(1.f, 1.f);
            sc[0] = sc[1] = sc[2] = sc[3] = *(uint32_t*)&one;
        }

        const uint32_t bufb = sBuf + (kc % 3) * CHUNK_BYTES;
#pragma unroll
        for (int ks = 0; ks < 4; ks++) {
            uint32_t aR0[4], aR1[4];
            aR0[0] = hmul2u(xF[0][ks][0], sc[0]);
            aR0[1] = hmul2u(xF[0][ks][1], sc[1]);
            aR0[2] = hmul2u(xF[0][ks][2], sc[0]);
            aR0[3] = hmul2u(xF[0][ks][3], sc[1]);
            aR1[0] = hmul2u(xF[1][ks][0], sc[2]);
            aR1[1] = hmul2u(xF[1][ks][1], sc[3]);
            aR1[2] = hmul2u(xF[1][ks][2], sc[2]);
            aR1[3] = hmul2u(xF[1][ks][3], sc[3]);
#pragma unroll
            for (int p = 0; p < 4; p++) {
                int r = p * 16 + (lane & 15);
                uint32_t off = (uint32_t)(r * 128 + (ks * 16 + ((lane >> 4) << 3)) * 2);
                off ^= (off >> 3) & 0x70;
                uint32_t b0[2], b1[2];
                ldsm_x4(b0[0], b1[0], b0[1], b1[1], bufb + off);
                mma16816(acc[0][2 * p],     aR0, b0);
                mma16816(acc[0][2 * p + 1], aR0, b1);
                mma16816(acc[1][2 * p],     aR1, b0);
                mma16816(acc[1][2 * p + 1], aR1, b1);
            }
        }
        if (lane == 0)
            asm volatile("mbarrier.arrive.shared.b64 _, [%0];"
                         :: "r"(mempty + (kc % 3) * 8) : "memory");
    }
#undef BULK_ISSUE

    int dd[4];
#pragma unroll
    for (int q = 0; q < 4; q++) dd[q] = (eg[q] < EE) ? DST[eg[q]] : -1;
#pragma unroll
    for (int mt = 0; mt < 2; mt++) {
#pragma unroll
        for (int j = 0; j < 8; j++) {
            int c = j * 8 + m2;
            if (dd[2 * mt] >= 0) {
                atomicAdd(&SS[(size_t)dd[2 * mt] * 64 + c],     acc[mt][j][0]);
                atomicAdd(&SS[(size_t)dd[2 * mt] * 64 + c + 1], acc[mt][j][1]);
            }
            if (dd[2 * mt + 1] >= 0) {
                atomicAdd(&SS[(size_t)dd[2 * mt + 1] * 64 + c],     acc[mt][j][2]);
                atomicAdd(&SS[(size_t)dd[2 * mt + 1] * 64 + c + 1], acc[mt][j][3]);
            }
        }
    }
}

// Y[n,:] = relu( SS[n,:]/max(cnt,1) + Xprev[n,:] @ root + bias )
// 128-row tiles, 2 rows/thread; grid 782 (391 b-part then 391 a-part)
__global__ void __launch_bounds__(256) k_finalize2(
    const float* __restrict__ Xb_, const float* __restrict__ SSb_,
    const float* __restrict__ CNTb_, const float* __restrict__ Wab,
    const float* __restrict__ bab, float* __restrict__ Yb_,
    const float* __restrict__ Xa_, const float* __restrict__ SSa_,
    const float* __restrict__ CNTa_, const float* __restrict__ Wba,
    const float* __restrict__ bba, float* __restrict__ Ya_)
{
    extern __shared__ __align__(16) float pool[];
    float* sW = pool;
    float* sB = pool + 4096;
    float* sX = pool + 4160;
    int bid = blockIdx.x;
    const float* Xp; const float* SS; const float* CNT; const float* W; const float* b;
    float* Y; int N;
    if (bid < NTILE) { Xp = Xb_; SS = SSb_; CNT = CNTb_; W = Wab; b = bab; Y = Yb_; N = NB; }
    else { bid -= NTILE; Xp = Xa_; SS = SSa_; CNT = CNTa_; W = Wba; b = bba; Y = Ya_; N = NA; }
    int tid = threadIdx.x;
    for (int i = tid; i < 1024; i += 256)
        ((float4*)sW)[i] = ((const float4*)W)[i];
    if (tid < 64) sB[tid] = b[tid];
    int n0 = bid * 128;
    int r = tid >> 2, c0 = (tid & 3) * 16;
    int nr0 = n0 + r, nr1 = n0 + r + 64;
#pragma unroll
    for (int h = 0; h < 2; h++) {
        int n = h ? nr1 : nr0;
        int rr = h ? r + 64 : r;
        float4* sxp = (float4*)(sX + rr * SXW + c0);
        if (n < N) {
            const float4* xr = (const float4*)(Xp + (size_t)n * 64 + c0);
#pragma unroll
            for (int k = 0; k < 4; k++) sxp[k] = xr[k];
        } else {
            float4 z = {0.f, 0.f, 0.f, 0.f};
#pragma unroll
            for (int k = 0; k < 4; k++) sxp[k] = z;
        }
    }
    __syncthreads();
    int o0 = (tid & 3) * 16;
    float acc0[16], acc1[16];
#pragma unroll
    for (int j = 0; j < 16; j++) { acc0[j] = sB[o0 + j]; acc1[j] = sB[o0 + j]; }
    const float* sx0 = sX + r * SXW;
    const float* sx1 = sX + (r + 64) * SXW;
#pragma unroll 8
    for (int d = 0; d < 64; d++) {
        float xv0 = sx0[d], xv1 = sx1[d];
        const float4* wr = (const float4*)(sW + d * 64 + o0);
        float4 w0 = wr[0], w1 = wr[1], w2 = wr[2], w3 = wr[3];
        acc0[0]  += xv0 * w0.x; acc0[1]  += xv0 * w0.y; acc0[2]  += xv0 * w0.z; acc0[3]  += xv0 * w0.w;
        acc0[4]  += xv0 * w1.x; acc0[5]  += xv0 * w1.y; acc0[6]  += xv0 * w1.z; acc0[7]  += xv0 * w1.w;
        acc0[8]  += xv0 * w2.x; acc0[9]  += xv0 * w2.y; acc0[10] += xv0 * w2.z; acc0[11] += xv0 * w2.w;
        acc0[12] += xv0 * w3.x; acc0[13] += xv0 * w3.y; acc0[14] += xv0 * w3.z; acc0[15] += xv0 * w3.w;
        acc1[0]  += xv1 * w0.x; acc1[1]  += xv1 * w0.y; acc1[2]  += xv1 * w0.z; acc1[3]  += xv1 * w0.w;
        acc1[4]  += xv1 * w1.x; acc1[5]  += xv1 * w1.y; acc1[6]  += xv1 * w1.z; acc1[7]  += xv1 * w1.w;
        acc1[8]  += xv1 * w2.x; acc1[9]  += xv1 * w2.y; acc1[10] += xv1 * w2.z; acc1[11] += xv1 * w2.w;
        acc1[12] += xv1 * w3.x; acc1[13] += xv1 * w3.y; acc1[14] += xv1 * w3.z; acc1[15] += xv1 * w3.w;
    }
    if (nr0 < N) {
        float ic = 1.f / fmaxf(CNT[nr0], 1.f);
        const float4* sp = (const float4*)(SS + (size_t)nr0 * 64 + o0);
        float4* yp = (float4*)(Y + (size_t)nr0 * 64 + o0);
#pragma unroll
        for (int k = 0; k < 4; k++) {
            float4 s = sp[k];
            float4 v;
            v.x = fmaxf(acc0[4 * k + 0] + s.x * ic, 0.f);
            v.y = fmaxf(acc0[4 * k + 1] + s.y * ic, 0.f);
            v.z = fmaxf(acc0[4 * k + 2] + s.z * ic, 0.f);
            v.w = fmaxf(acc0[4 * k + 3] + s.w * ic, 0.f);
            yp[k] = v;
        }
    }
    if (nr1 < N) {
        float ic = 1.f / fmaxf(CNT[nr1], 1.f);
        const float4* sp = (const float4*)(SS + (size_t)nr1 * 64 + o0);
        float4* yp = (float4*)(Y + (size_t)nr1 * 64 + o0);
#pragma unroll
        for (int k = 0; k < 4; k++) {
            float4 s = sp[k];
            float4 v;
            v.x = fmaxf(acc1[4 * k + 0] + s.x * ic, 0.f);
            v.y = fmaxf(acc1[4 * k + 1] + s.y * ic, 0.f);
            v.z = fmaxf(acc1[4 * k + 2] + s.z * ic, 0.f);
            v.w = fmaxf(acc1[4 * k + 3] + s.w * ic, 0.f);
            yp[k] = v;
        }
    }
}

// ---------------- launcher ----------------
static void* sym(const void* s) {
    void* p = nullptr;
    cudaGetSymbolAddress(&p, s);
    return p;
}

extern "C" void kernel_launch(void* const* d_in, const int* in_sizes, int n_in,
                              void* d_out, int out_size)
{
    const int*   x_a      = (const int*)d_in[0];
    const int*   x_b      = (const int*)d_in[1];
    const int*   ei_ab    = (const int*)d_in[2];   // [2,E]
    const int*   ei_ba    = (const int*)d_in[3];
    const float* ea_ab    = (const float*)d_in[4];
    const float* ea_ba    = (const float*)d_in[5];
    const float* emb_a    = (const float*)d_in[6];
    const float* emb_b    = (const float*)d_in[7];
    const float* Wn_a     = (const float*)d_in[8];
    const float* bn_a     = (const float*)d_in[9];
    const float* Wn_b     = (const float*)d_in[10];
    const float* bn_b     = (const float*)d_in[11];
    const float* W1_ab    = (const float*)d_in[12];
    const float* b1_ab    = (const float*)d_in[13];
    const float* W2_ab    = (const float*)d_in[14];
    const float* b2_ab    = (const float*)d_in[15];
    const float* W1_ba    = (const float*)d_in[16];
    const float* b1_ba    = (const float*)d_in[17];
    const float* W2_ba    = (const float*)d_in[18];
    const float* b2_ba    = (const float*)d_in[19];
    const float* root0_ab = (const float*)d_in[20];
    const float* bias0_ab = (const float*)d_in[21];
    const float* root0_ba = (const float*)d_in[22];
    const float* bias0_ba = (const float*)d_in[23];
    const float* root1_ab = (const float*)d_in[24];
    const float* bias1_ab = (const float*)d_in[25];
    const float* root1_ba = (const float*)d_in[26];
    const float* bias1_ba = (const float*)d_in[27];

    float*  xa0 = (float*)sym(g_xa0);
    float*  xb0 = (float*)sym(g_xb0);
    float*  xa1 = (float*)sym(g_xa1);
    float*  xb1 = (float*)sym(g_xb1);
    __half* hab = (__half*)sym(g_hab);
    __half* hba = (__half*)sym(g_hba);
    __half* wnab = (__half*)sym(g_wn_ab);
    __half* wnba = (__half*)sym(g_wn_ba);
    float*  ss  = (float*)sym(g_ss);
    float*  cnt = (float*)sym(g_cnt);
    float*  ssa = ss;
    float*  ssb = ss + (size_t)NA * DD;
    float*  cnta = cnt;
    float*  cntb = cnt + NA;

    const int* src_ab = ei_ab;
    const int* dst_ab = ei_ab + EE;
    const int* src_ba = ei_ba;
    const int* dst_ba = ei_ba + EE;

    float* out = (float*)d_out;

    cudaFuncSetAttribute(k_conv2, cudaFuncAttributeMaxDynamicSharedMemorySize, CONV_SMEM);
    cudaFuncSetAttribute(k_ne, cudaFuncAttributeMaxDynamicSharedMemorySize, NF_SMEM);
    cudaFuncSetAttribute(k_finalize2, cudaFuncAttributeMaxDynamicSharedMemorySize, NF_SMEM);

    // 1. zero ss + cnt
    const int ZN = (NA + NB) * DD + (NA + NB);
    k_zero2<<<(ZN + 255) / 256, 256>>>(ss, cnt);

    // 2. pack W2+b2 + degree counts (merged, independent)
    k_packcnt<<<PK_BLKS + CNT_BLKS, 256>>>(W2_ab, b2_ab, wnab, W2_ba, b2_ba, wnba,
                                           dst_ab, dst_ba, cnta, cntb);

    // 3. node features (128-row tiles) + edge MLP (merged)
    k_ne<<<2 * NTILE + 944, 256, NF_SMEM>>>(emb_a, x_a, Wn_a, bn_a, xa0,
                                            emb_b, x_b, Wn_b, bn_b, xb0,
                                            ea_ab, W1_ab, b1_ab, hab,
                                            ea_ba, W1_ba, b1_ba, hba);

    // 4. conv layer 0
    k_conv2<<<2 * NBLK_C, 256, CONV_SMEM>>>(xa0, hab, wnab, src_ab, dst_ab, ssb,
                                            xb0, hba, wnba, src_ba, dst_ba, ssa);

    // 5. finalize layer 0
    k_finalize2<<<2 * NTILE, 256, NF_SMEM>>>(xb0, ssb, cntb, root0_ab, bias0_ab, xb1,
                                             xa0, ssa, cnta, root0_ba, bias0_ba, xa1);

    // 6. re-zero ss
    k_zero<<<((NA + NB) * DD + 255) / 256, 256>>>(ss, (NA + NB) * DD);

    // 7. conv layer 1
    k_conv2<<<2 * NBLK_C, 256, CONV_SMEM>>>(xa1, hab, wnab, src_ab, dst_ab, ssb,
                                            xb1, hba, wnba, src_ba, dst_ba, ssa);

    // 8. finalize layer 1
    k_finalize2<<<2 * NTILE, 256, NF_SMEM>>>(xb1, ssb, cntb, root1_ab, bias1_ab, out + (size_t)NA * DD,
                                             xa1, ssa, cnta, root1_ba, bias1_ba, out);
}